// round 14
// baseline (speedup 1.0000x reference)
#include <cuda_runtime.h>
#include <cuda_fp16.h>
#include <stdint.h>
#include <math.h>

// ---------------- problem constants ----------------
#define Bsz   8
#define Tlen  4096
#define Cdim  512
#define Hdim  512
#define Mtot  (Bsz * Tlen)          // 32768 rows
#define NCH   64
#define CHUNK (Tlen / NCH)          // 64

// ---------------- GEMM tiling ----------------
#define BM     128
#define BN     128
#define STAGES 3
#define NIT    16                   // K=1024 / 64
#define AROWB  144                  // 128B row + 16B pad (conflict-free ldmatrix)
#define ASTG   (BM * AROWB)         // 18432
#define BSTG   (BN * AROWB)         // 18432
#define STG    (ASTG + BSTG)        // 36864
#define SMEMT  (STAGES * STG)       // 110592

// ---------------- device scratch ----------------
__device__ __half g_z[(size_t)Mtot * Hdim];
__device__ __half g_f[(size_t)Mtot * Hdim];
__device__ __half g_o[(size_t)Mtot * Hdim];
__device__ float g_P[Bsz * NCH * Hdim];
__device__ float g_L[Bsz * NCH * Hdim];
__device__ __half g_xh[(size_t)Mtot * Cdim];
__device__ __half g_wt[3][(size_t)Hdim * 2 * Cdim];   // [gate][h*1024 + kk], fp16

// ---------------- PTX helpers ----------------
__device__ __forceinline__ uint32_t smem_u32(const void* p) {
    uint32_t a;
    asm("{ .reg .u64 t; cvta.to.shared.u64 t, %1; cvt.u32.u64 %0, t; }" : "=r"(a) : "l"(p));
    return a;
}
__device__ __forceinline__ void cpa16(uint32_t dst, const void* src, uint32_t sz) {
    asm volatile("cp.async.cg.shared.global [%0], [%1], 16, %2;"
                 :: "r"(dst), "l"(src), "r"(sz) : "memory");
}
#define CP_COMMIT() asm volatile("cp.async.commit_group;" ::: "memory")
#define CP_WAIT1()  asm volatile("cp.async.wait_group 1;" ::: "memory")

#define LDSM4(r, a) \
    asm volatile("ldmatrix.sync.aligned.m8n8.x4.shared.b16 {%0,%1,%2,%3}, [%4];" \
        : "=r"((r)[0]), "=r"((r)[1]), "=r"((r)[2]), "=r"((r)[3]) : "r"(a))

__device__ __forceinline__ void mma16816(float* c, const uint32_t* a,
                                         uint32_t b0, uint32_t b1) {
    asm volatile(
        "mma.sync.aligned.m16n8k16.row.col.f32.f16.f16.f32 "
        "{%0,%1,%2,%3}, {%4,%5,%6,%7}, {%8,%9}, {%0,%1,%2,%3};"
        : "+f"(c[0]), "+f"(c[1]), "+f"(c[2]), "+f"(c[3])
        : "r"(a[0]), "r"(a[1]), "r"(a[2]), "r"(a[3]), "r"(b0), "r"(b1));
}

// ---------------- combined prep kernel ----------------
#define PX_BLOCKS 2048    // 2048 blocks * 256 thr * 8 float4 = Mtot*Cdim/4

__global__ __launch_bounds__(256) void prep_all(
    const float* __restrict__ x,
    const float* __restrict__ wz, const float* __restrict__ wf, const float* __restrict__ wo)
{
    __shared__ float tile[32][33];
    if (blockIdx.x < PX_BLOCKS) {
        // x -> fp16, 8 float4 per thread, loads front-batched (MLP=8)
        const float4* xv = (const float4*)x;
        __half2* hp = (__half2*)g_xh;
        const size_t i0 = (size_t)blockIdx.x * 2048 + threadIdx.x;
        float4 v[8];
        #pragma unroll
        for (int j = 0; j < 8; j++) v[j] = xv[i0 + j * 256];
        #pragma unroll
        for (int j = 0; j < 8; j++) {
            const size_t i = i0 + j * 256;
            hp[i*2]   = __floats2half2_rn(v[j].x, v[j].y);
            hp[i*2+1] = __floats2half2_rn(v[j].z, v[j].w);
        }
    } else {
        const int bid = blockIdx.x - PX_BLOCKS;       // 0..1535
        const int gate = bid >> 9;
        const int rem = bid & 511;
        const int kk0 = (rem & 31) * 32, h0 = (rem >> 5) * 32;
        const float* W = (gate == 0) ? wz : ((gate == 1) ? wf : wo);
        const int tx = threadIdx.x & 31, ty = threadIdx.x >> 5;   // 32 x 8
        for (int i = ty; i < 32; i += 8)
            tile[i][tx] = W[(size_t)(kk0 + i) * Hdim + h0 + tx];
        __syncthreads();
        for (int i = ty; i < 32; i += 8) {
            float v = tile[tx][i];                                 // W[kk0+tx][h0+i]
            g_wt[gate][(size_t)(h0 + i) * 1024 + kk0 + tx] = __float2half(v);
        }
    }
}

// ---------------- HMMA GEMM (grid-tiled, BK=64 stages) ----------------
// grid (N/BN=4, M/BM=256, 3 gates), 256 threads (8 warps as 4m x 2n)
__global__ __launch_bounds__(256, 2) void gate_gemm_mma(
    const float* __restrict__ bz, const float* __restrict__ bf_,
    const float* __restrict__ bo)
{
    extern __shared__ char smem[];
    const uint32_t sb = smem_u32(smem);
    const int tid = threadIdx.x, lane = tid & 31, wid = tid >> 5;
    const int wm = wid & 3, wn = wid >> 2;
    const int gate = blockIdx.z;
    const int n0 = blockIdx.x * BN;
    const int m0 = blockIdx.y * BM;

    const float* bias = (gate == 0) ? bz : ((gate == 1) ? bf_ : bo);
    __half* outg      = (gate == 0) ? g_z : ((gate == 1) ? g_f : g_o);
    const __half* wt = g_wt[gate];

    const int lrow = tid >> 3;        // 0..31 (rows lrow, +32, +64, +96)
    const int lseg = tid & 7;         // 16B segment within 128B row

    auto load_stage = [&](int it) {
        const int kidx = it * 64;                 // 0..960 (never crosses 512)
        const int shift = (kidx < 512) ? 1 : 0;   // tap t-1 vs t
        const int acolB = ((kidx & 511) * 2) + lseg * 16;
        const int wcolB = kidx * 2 + lseg * 16;
        const uint32_t as = sb + (it % STAGES) * STG;
        const uint32_t bs = as + ASTG;
        #pragma unroll
        for (int h = 0; h < 4; h++) {
            const int r = lrow + h * 32;
            const int m = m0 + r;
            const char* src = (const char*)g_xh + (size_t)(m - shift) * 1024 + acolB;
            uint32_t sz = 16;
            if (shift && ((m & (Tlen - 1)) == 0)) { sz = 0; src = (const char*)g_xh; }
            cpa16(as + r * AROWB + lseg * 16, src, sz);
        }
        #pragma unroll
        for (int h = 0; h < 4; h++) {
            const int r = lrow + h * 32;
            const char* src = (const char*)wt + (size_t)(n0 + r) * 2048 + wcolB;
            cpa16(bs + r * AROWB + lseg * 16, src, 16);
        }
    };

    load_stage(0); CP_COMMIT();
    load_stage(1); CP_COMMIT();

    float acc[2][8][4];
    #pragma unroll
    for (int f = 0; f < 2; f++)
        #pragma unroll
        for (int n = 0; n < 8; n++)
            #pragma unroll
            for (int q = 0; q < 4; q++) acc[f][n][q] = 0.0f;

    const uint32_t aBase = (uint32_t)((wm * 32 + (lane & 15)) * AROWB + (lane >> 4) * 16);
    const uint32_t bBase = (uint32_t)((wn * 64 + (lane & 15)) * AROWB + (lane >> 4) * 16);

    for (int it = 0; it < NIT; it++) {
        CP_WAIT1();
        __syncthreads();
        // slot (it+2)%3 == (it-1)%3, fully consumed before the barrier above
        if (it + 2 < NIT) load_stage(it + 2);
        CP_COMMIT();

        const uint32_t as = sb + (it % STAGES) * STG;
        const uint32_t bs = as + ASTG;
        #pragma unroll
        for (int jk = 0; jk < 4; jk++) {
            uint32_t af[2][4], bg[4][4];
            LDSM4(af[0], as + aBase + jk * 32);
            LDSM4(af[1], as + aBase + 16 * AROWB + jk * 32);
            #pragma unroll
            for (int g = 0; g < 4; g++)
                LDSM4(bg[g], bs + bBase + g * 16 * AROWB + jk * 32);
            #pragma unroll
            for (int f = 0; f < 2; f++)
                #pragma unroll
                for (int nt = 0; nt < 8; nt++) {
                    const int g = nt >> 1, p = nt & 1;
                    mma16816(acc[f][nt], af[f], bg[g][p], bg[g][p + 2]);
                }
        }
    }

    // epilogue: bias + activation + fp16 stores
    #pragma unroll
    for (int f = 0; f < 2; f++) {
        const int rbase = m0 + wm * 32 + f * 16 + (lane >> 2);
        #pragma unroll
        for (int nt = 0; nt < 8; nt++) {
            const int col = n0 + wn * 64 + nt * 8 + (lane & 3) * 2;
            const float b0 = __ldg(bias + col), b1 = __ldg(bias + col + 1);
            float v0 = acc[f][nt][0] + b0, v1 = acc[f][nt][1] + b1;
            float v2 = acc[f][nt][2] + b0, v3 = acc[f][nt][3] + b1;
            if (gate == 0) {
                v0 = tanhf(v0); v1 = tanhf(v1); v2 = tanhf(v2); v3 = tanhf(v3);
            } else {
                v0 = 1.0f / (1.0f + __expf(-v0));
                v1 = 1.0f / (1.0f + __expf(-v1));
                v2 = 1.0f / (1.0f + __expf(-v2));
                v3 = 1.0f / (1.0f + __expf(-v3));
            }
            *(__half2*)(outg + (size_t)rbase * Hdim + col)       = __floats2half2_rn(v0, v1);
            *(__half2*)(outg + (size_t)(rbase + 8) * Hdim + col) = __floats2half2_rn(v2, v3);
        }
    }
}

// ---------------- scan (chunked linear recurrence, half2-vectorized) ----------------
__global__ __launch_bounds__(256) void chunk_reduce()
{
    const int t2 = threadIdx.x;                   // half2 index: h = 2*t2, 2*t2+1
    const int c = blockIdx.x, b = blockIdx.y;
    size_t base = ((size_t)(b * Tlen + c * CHUNK) * Hdim >> 1) + t2;
    const __half2* F = (const __half2*)g_f;
    const __half2* Z = (const __half2*)g_z;
    float P0 = 1.f, P1 = 1.f, L0 = 0.f, L1 = 0.f;
    #pragma unroll 8
    for (int i = 0; i < CHUNK; i++) {
        const size_t idx = base + (size_t)i * (Hdim / 2);
        float2 f2 = __half22float2(F[idx]);
        float2 z2 = __half22float2(Z[idx]);
        L0 = fmaf(f2.x, L0, (1.0f - f2.x) * z2.x);
        L1 = fmaf(f2.y, L1, (1.0f - f2.y) * z2.y);
        P0 *= f2.x; P1 *= f2.y;
    }
    const size_t ci = (size_t)(b * NCH + c) * Hdim + 2 * t2;
    *(float2*)&g_P[ci] = make_float2(P0, P1);
    *(float2*)&g_L[ci] = make_float2(L0, L1);
}

// Apply with inline lookback: block (b,c) first combines the published
// per-chunk carries of chunks 0..c-1 (batched 8-wide loads, L2-hot from
// chunk_reduce; identity-padded partial batches keep the combine order
// bit-identical to the old chunk_prefix), then scans its own chunk.
__global__ __launch_bounds__(256) void chunk_apply(float* __restrict__ out)
{
    const int t2 = threadIdx.x;
    const int c = blockIdx.x, b = blockIdx.y;
    const float2* P2 = (const float2*)g_P;
    const float2* L2 = (const float2*)g_L;

    float2 hc = make_float2(0.f, 0.f);
    for (int c0 = 0; c0 < c; c0 += 8) {
        float2 P[8], L[8];
        #pragma unroll
        for (int j = 0; j < 8; j++) {
            if (c0 + j < c) {
                const size_t idx = ((size_t)(b * NCH + c0 + j) * Hdim >> 1) + t2;
                P[j] = P2[idx];
                L[j] = L2[idx];
            } else {
                P[j] = make_float2(1.f, 1.f);
                L[j] = make_float2(0.f, 0.f);
            }
        }
        #pragma unroll
        for (int j = 0; j < 8; j++) {
            hc.x = fmaf(P[j].x, hc.x, L[j].x);
            hc.y = fmaf(P[j].y, hc.y, L[j].y);
        }
    }

    size_t base = ((size_t)(b * Tlen + c * CHUNK) * Hdim >> 1) + t2;
    const __half2* F = (const __half2*)g_f;
    const __half2* Z = (const __half2*)g_z;
    const __half2* O = (const __half2*)g_o;
    #pragma unroll 4
    for (int i = 0; i < CHUNK; i++) {
        const size_t idx = base + (size_t)i * (Hdim / 2);
        float2 f2 = __half22float2(F[idx]);
        float2 z2 = __half22float2(Z[idx]);
        float2 o2 = __half22float2(O[idx]);
        hc.x = fmaf(f2.x, hc.x, (1.0f - f2.x) * z2.x);
        hc.y = fmaf(f2.y, hc.y, (1.0f - f2.y) * z2.y);
        ((float2*)out)[idx] = make_float2(hc.x * o2.x, hc.y * o2.y);
    }
}

// ---------------- launch ----------------
extern "C" void kernel_launch(void* const* d_in, const int* in_sizes, int n_in,
                              void* d_out, int out_size)
{
    const float* x  = (const float*)d_in[0];
    const float* wz = (const float*)d_in[1];
    const float* bz = (const float*)d_in[2];
    const float* wf = (const float*)d_in[3];
    const float* bf = (const float*)d_in[4];
    const float* wo = (const float*)d_in[5];
    const float* bo = (const float*)d_in[6];
    float* out = (float*)d_out;

    cudaFuncSetAttribute(gate_gemm_mma, cudaFuncAttributeMaxDynamicSharedMemorySize, SMEMT);

    prep_all<<<PX_BLOCKS + 1536, 256>>>(x, wz, wf, wo);

    gate_gemm_mma<<<dim3(Hdim / BN, Mtot / BM, 3), 256, SMEMT>>>(bz, bf, bo);

    chunk_reduce<<<dim3(NCH, Bsz), 256>>>();
    chunk_apply<<<dim3(NCH, Bsz), 256>>>(out);
}

// round 15
// speedup vs baseline: 1.4665x; 1.4665x over previous
#include <cuda_runtime.h>
#include <cuda_fp16.h>
#include <stdint.h>
#include <math.h>

// ---------------- problem constants ----------------
#define Bsz   8
#define Tlen  4096
#define Cdim  512
#define Hdim  512
#define Mtot  (Bsz * Tlen)          // 32768 rows
#define NCH   64
#define CHUNK (Tlen / NCH)          // 64

// ---------------- GEMM tiling ----------------
#define BM     128
#define BN     128
#define STAGES 3
#define NIT    16                   // K=1024 / 64
#define AROWB  144                  // 128B row + 16B pad (conflict-free ldmatrix)
#define ASTG   (BM * AROWB)         // 18432
#define BSTG   (BN * AROWB)         // 18432
#define STG    (ASTG + BSTG)        // 36864
#define SMEMT  (STAGES * STG)       // 110592

// ---------------- device scratch ----------------
__device__ __half g_z[(size_t)Mtot * Hdim];
__device__ __half g_f[(size_t)Mtot * Hdim];
__device__ __half g_o[(size_t)Mtot * Hdim];
__device__ float g_P[Bsz * NCH * Hdim];
__device__ float g_L[Bsz * NCH * Hdim];
__device__ float g_hin[Bsz * NCH * Hdim];
__device__ __half g_xh[(size_t)Mtot * Cdim];
__device__ __half g_wt[3][(size_t)Hdim * 2 * Cdim];   // [gate][h*1024 + kk], fp16

// ---------------- PTX helpers ----------------
__device__ __forceinline__ uint32_t smem_u32(const void* p) {
    uint32_t a;
    asm("{ .reg .u64 t; cvta.to.shared.u64 t, %1; cvt.u32.u64 %0, t; }" : "=r"(a) : "l"(p));
    return a;
}
__device__ __forceinline__ void cpa16(uint32_t dst, const void* src, uint32_t sz) {
    asm volatile("cp.async.cg.shared.global [%0], [%1], 16, %2;"
                 :: "r"(dst), "l"(src), "r"(sz) : "memory");
}
#define CP_COMMIT() asm volatile("cp.async.commit_group;" ::: "memory")
#define CP_WAIT1()  asm volatile("cp.async.wait_group 1;" ::: "memory")

#define LDSM4(r, a) \
    asm volatile("ldmatrix.sync.aligned.m8n8.x4.shared.b16 {%0,%1,%2,%3}, [%4];" \
        : "=r"((r)[0]), "=r"((r)[1]), "=r"((r)[2]), "=r"((r)[3]) : "r"(a))

__device__ __forceinline__ void mma16816(float* c, const uint32_t* a,
                                         uint32_t b0, uint32_t b1) {
    asm volatile(
        "mma.sync.aligned.m16n8k16.row.col.f32.f16.f16.f32 "
        "{%0,%1,%2,%3}, {%4,%5,%6,%7}, {%8,%9}, {%0,%1,%2,%3};"
        : "+f"(c[0]), "+f"(c[1]), "+f"(c[2]), "+f"(c[3])
        : "r"(a[0]), "r"(a[1]), "r"(a[2]), "r"(a[3]), "r"(b0), "r"(b1));
}

// ---------------- combined prep kernel ----------------
#define PX_BLOCKS 2048    // 2048 blocks * 256 thr * 8 float4 = Mtot*Cdim/4

__global__ __launch_bounds__(256) void prep_all(
    const float* __restrict__ x,
    const float* __restrict__ wz, const float* __restrict__ wf, const float* __restrict__ wo)
{
    __shared__ float tile[32][33];
    if (blockIdx.x < PX_BLOCKS) {
        // x -> fp16, 8 float4 per thread, loads front-batched (MLP=8)
        const float4* xv = (const float4*)x;
        __half2* hp = (__half2*)g_xh;
        const size_t i0 = (size_t)blockIdx.x * 2048 + threadIdx.x;
        float4 v[8];
        #pragma unroll
        for (int j = 0; j < 8; j++) v[j] = xv[i0 + j * 256];
        #pragma unroll
        for (int j = 0; j < 8; j++) {
            const size_t i = i0 + j * 256;
            hp[i*2]   = __floats2half2_rn(v[j].x, v[j].y);
            hp[i*2+1] = __floats2half2_rn(v[j].z, v[j].w);
        }
    } else {
        const int bid = blockIdx.x - PX_BLOCKS;       // 0..1535
        const int gate = bid >> 9;
        const int rem = bid & 511;
        const int kk0 = (rem & 31) * 32, h0 = (rem >> 5) * 32;
        const float* W = (gate == 0) ? wz : ((gate == 1) ? wf : wo);
        const int tx = threadIdx.x & 31, ty = threadIdx.x >> 5;   // 32 x 8
        for (int i = ty; i < 32; i += 8)
            tile[i][tx] = W[(size_t)(kk0 + i) * Hdim + h0 + tx];
        __syncthreads();
        for (int i = ty; i < 32; i += 8) {
            float v = tile[tx][i];                                 // W[kk0+tx][h0+i]
            g_wt[gate][(size_t)(h0 + i) * 1024 + kk0 + tx] = __float2half(v);
        }
    }
}

// ---------------- HMMA GEMM (grid-tiled, BK=64 stages) ----------------
// grid (N/BN=4, M/BM=256, 3 gates), 256 threads (8 warps as 4m x 2n)
__global__ __launch_bounds__(256, 2) void gate_gemm_mma(
    const float* __restrict__ bz, const float* __restrict__ bf_,
    const float* __restrict__ bo)
{
    extern __shared__ char smem[];
    const uint32_t sb = smem_u32(smem);
    const int tid = threadIdx.x, lane = tid & 31, wid = tid >> 5;
    const int wm = wid & 3, wn = wid >> 2;
    const int gate = blockIdx.z;
    const int n0 = blockIdx.x * BN;
    const int m0 = blockIdx.y * BM;

    const float* bias = (gate == 0) ? bz : ((gate == 1) ? bf_ : bo);
    __half* outg      = (gate == 0) ? g_z : ((gate == 1) ? g_f : g_o);
    const __half* wt = g_wt[gate];

    const int lrow = tid >> 3;        // 0..31 (rows lrow, +32, +64, +96)
    const int lseg = tid & 7;         // 16B segment within 128B row

    auto load_stage = [&](int it) {
        const int kidx = it * 64;                 // 0..960 (never crosses 512)
        const int shift = (kidx < 512) ? 1 : 0;   // tap t-1 vs t
        const int acolB = ((kidx & 511) * 2) + lseg * 16;
        const int wcolB = kidx * 2 + lseg * 16;
        const uint32_t as = sb + (it % STAGES) * STG;
        const uint32_t bs = as + ASTG;
        #pragma unroll
        for (int h = 0; h < 4; h++) {
            const int r = lrow + h * 32;
            const int m = m0 + r;
            const char* src = (const char*)g_xh + (size_t)(m - shift) * 1024 + acolB;
            uint32_t sz = 16;
            if (shift && ((m & (Tlen - 1)) == 0)) { sz = 0; src = (const char*)g_xh; }
            cpa16(as + r * AROWB + lseg * 16, src, sz);
        }
        #pragma unroll
        for (int h = 0; h < 4; h++) {
            const int r = lrow + h * 32;
            const char* src = (const char*)wt + (size_t)(n0 + r) * 2048 + wcolB;
            cpa16(bs + r * AROWB + lseg * 16, src, 16);
        }
    };

    load_stage(0); CP_COMMIT();
    load_stage(1); CP_COMMIT();

    float acc[2][8][4];
    #pragma unroll
    for (int f = 0; f < 2; f++)
        #pragma unroll
        for (int n = 0; n < 8; n++)
            #pragma unroll
            for (int q = 0; q < 4; q++) acc[f][n][q] = 0.0f;

    const uint32_t aBase = (uint32_t)((wm * 32 + (lane & 15)) * AROWB + (lane >> 4) * 16);
    const uint32_t bBase = (uint32_t)((wn * 64 + (lane & 15)) * AROWB + (lane >> 4) * 16);

    for (int it = 0; it < NIT; it++) {
        CP_WAIT1();
        __syncthreads();
        // slot (it+2)%3 == (it-1)%3, fully consumed before the barrier above
        if (it + 2 < NIT) load_stage(it + 2);
        CP_COMMIT();

        const uint32_t as = sb + (it % STAGES) * STG;
        const uint32_t bs = as + ASTG;
        #pragma unroll
        for (int jk = 0; jk < 4; jk++) {
            uint32_t af[2][4], bg[4][4];
            LDSM4(af[0], as + aBase + jk * 32);
            LDSM4(af[1], as + aBase + 16 * AROWB + jk * 32);
            #pragma unroll
            for (int g = 0; g < 4; g++)
                LDSM4(bg[g], bs + bBase + g * 16 * AROWB + jk * 32);
            #pragma unroll
            for (int f = 0; f < 2; f++)
                #pragma unroll
                for (int nt = 0; nt < 8; nt++) {
                    const int g = nt >> 1, p = nt & 1;
                    mma16816(acc[f][nt], af[f], bg[g][p], bg[g][p + 2]);
                }
        }
    }

    // epilogue: bias + activation + fp16 stores
    #pragma unroll
    for (int f = 0; f < 2; f++) {
        const int rbase = m0 + wm * 32 + f * 16 + (lane >> 2);
        #pragma unroll
        for (int nt = 0; nt < 8; nt++) {
            const int col = n0 + wn * 64 + nt * 8 + (lane & 3) * 2;
            const float b0 = __ldg(bias + col), b1 = __ldg(bias + col + 1);
            float v0 = acc[f][nt][0] + b0, v1 = acc[f][nt][1] + b1;
            float v2 = acc[f][nt][2] + b0, v3 = acc[f][nt][3] + b1;
            if (gate == 0) {
                v0 = tanhf(v0); v1 = tanhf(v1); v2 = tanhf(v2); v3 = tanhf(v3);
            } else {
                v0 = 1.0f / (1.0f + __expf(-v0));
                v1 = 1.0f / (1.0f + __expf(-v1));
                v2 = 1.0f / (1.0f + __expf(-v2));
                v3 = 1.0f / (1.0f + __expf(-v3));
            }
            *(__half2*)(outg + (size_t)rbase * Hdim + col)       = __floats2half2_rn(v0, v1);
            *(__half2*)(outg + (size_t)(rbase + 8) * Hdim + col) = __floats2half2_rn(v2, v3);
        }
    }
}

// ---------------- scan (chunked linear recurrence, half2-vectorized) ----------------
__global__ __launch_bounds__(256) void chunk_reduce()
{
    const int t2 = threadIdx.x;                   // half2 index: h = 2*t2, 2*t2+1
    const int c = blockIdx.x, b = blockIdx.y;
    size_t base = ((size_t)(b * Tlen + c * CHUNK) * Hdim >> 1) + t2;
    const __half2* F = (const __half2*)g_f;
    const __half2* Z = (const __half2*)g_z;
    float P0 = 1.f, P1 = 1.f, L0 = 0.f, L1 = 0.f;
    #pragma unroll 4
    for (int i = 0; i < CHUNK; i++) {
        const size_t idx = base + (size_t)i * (Hdim / 2);
        float2 f2 = __half22float2(F[idx]);
        float2 z2 = __half22float2(Z[idx]);
        L0 = fmaf(f2.x, L0, (1.0f - f2.x) * z2.x);
        L1 = fmaf(f2.y, L1, (1.0f - f2.y) * z2.y);
        P0 *= f2.x; P1 *= f2.y;
    }
    const size_t ci = (size_t)(b * NCH + c) * Hdim + 2 * t2;
    *(float2*)&g_P[ci] = make_float2(P0, P1);
    *(float2*)&g_L[ci] = make_float2(L0, L1);
}

// Prefix over chunk carries, double-buffered batch prefetch: load batch j+1
// while running batch j's serial FMAs -> one exposed memory latency total.
__global__ __launch_bounds__(256) void chunk_prefix()
{
    const int t2 = threadIdx.x;                   // 2 channels per thread
    const int b = blockIdx.x;
    const float2* P2 = (const float2*)g_P;
    const float2* L2 = (const float2*)g_L;
    float2* H2 = (float2*)g_hin;

    float2 P[2][8], L[2][8];
    auto fetch = [&](int buf, int c0) {
        #pragma unroll
        for (int j = 0; j < 8; j++) {
            const size_t idx = ((size_t)(b * NCH + c0 + j) * Hdim >> 1) + t2;
            P[buf][j] = P2[idx];
            L[buf][j] = L2[idx];
        }
    };

    fetch(0, 0);
    float2 hc = make_float2(0.f, 0.f);
    for (int c0 = 0; c0 < NCH; c0 += 8) {
        const int buf = (c0 >> 3) & 1;
        if (c0 + 8 < NCH) fetch(buf ^ 1, c0 + 8);
        #pragma unroll
        for (int j = 0; j < 8; j++) {
            const size_t idx = ((size_t)(b * NCH + c0 + j) * Hdim >> 1) + t2;
            H2[idx] = hc;
            hc.x = fmaf(P[buf][j].x, hc.x, L[buf][j].x);
            hc.y = fmaf(P[buf][j].y, hc.y, L[buf][j].y);
        }
    }
}

__global__ __launch_bounds__(256) void chunk_apply(float* __restrict__ out)
{
    const int t2 = threadIdx.x;
    const int c = blockIdx.x, b = blockIdx.y;
    float2 hc = *(const float2*)&g_hin[(size_t)(b * NCH + c) * Hdim + 2 * t2];
    size_t base = ((size_t)(b * Tlen + c * CHUNK) * Hdim >> 1) + t2;
    const __half2* F = (const __half2*)g_f;
    const __half2* Z = (const __half2*)g_z;
    const __half2* O = (const __half2*)g_o;
    #pragma unroll 4
    for (int i = 0; i < CHUNK; i++) {
        const size_t idx = base + (size_t)i * (Hdim / 2);
        float2 f2 = __half22float2(F[idx]);
        float2 z2 = __half22float2(Z[idx]);
        float2 o2 = __half22float2(O[idx]);
        hc.x = fmaf(f2.x, hc.x, (1.0f - f2.x) * z2.x);
        hc.y = fmaf(f2.y, hc.y, (1.0f - f2.y) * z2.y);
        ((float2*)out)[idx] = make_float2(hc.x * o2.x, hc.y * o2.y);
    }
}

// ---------------- launch ----------------
extern "C" void kernel_launch(void* const* d_in, const int* in_sizes, int n_in,
                              void* d_out, int out_size)
{
    const float* x  = (const float*)d_in[0];
    const float* wz = (const float*)d_in[1];
    const float* bz = (const float*)d_in[2];
    const float* wf = (const float*)d_in[3];
    const float* bf = (const float*)d_in[4];
    const float* wo = (const float*)d_in[5];
    const float* bo = (const float*)d_in[6];
    float* out = (float*)d_out;

    cudaFuncSetAttribute(gate_gemm_mma, cudaFuncAttributeMaxDynamicSharedMemorySize, SMEMT);

    prep_all<<<PX_BLOCKS + 1536, 256>>>(x, wz, wf, wo);

    gate_gemm_mma<<<dim3(Hdim / BN, Mtot / BM, 3), 256, SMEMT>>>(bz, bf, bo);

    chunk_reduce<<<dim3(NCH, Bsz), 256>>>();
    chunk_prefix<<<Bsz, 256>>>();
    chunk_apply<<<dim3(NCH, Bsz), 256>>>(out);
}

// round 16
// speedup vs baseline: 1.5627x; 1.0656x over previous
#include <cuda_runtime.h>
#include <cuda_fp16.h>
#include <stdint.h>
#include <math.h>

// ---------------- problem constants ----------------
#define Bsz   8
#define Tlen  4096
#define Cdim  512
#define Hdim  512
#define Mtot  (Bsz * Tlen)          // 32768 rows
#define NCH   64
#define CHUNK (Tlen / NCH)          // 64

// ---------------- GEMM tiling ----------------
#define BM     128
#define BN     128
#define STAGES 3
#define NIT    16                   // K=1024 / 64
#define AROWB  144                  // 128B row + 16B pad (conflict-free ldmatrix)
#define ASTG   (BM * AROWB)         // 18432
#define BSTG   (BN * AROWB)         // 18432
#define STG    (ASTG + BSTG)        // 36864
#define SMEMT  (STAGES * STG)       // 110592

// ---------------- device scratch ----------------
__device__ __half g_z[(size_t)Mtot * Hdim];
__device__ __half g_f[(size_t)Mtot * Hdim];
__device__ __half g_o[(size_t)Mtot * Hdim];
__device__ float g_P[Bsz * NCH * Hdim];
__device__ float g_L[Bsz * NCH * Hdim];
__device__ float g_hin[Bsz * NCH * Hdim];
__device__ __half g_xh[(size_t)Mtot * Cdim];
__device__ __half g_wt[3][(size_t)Hdim * 2 * Cdim];   // [gate][h*1024 + kk], fp16

// ---------------- PTX helpers ----------------
__device__ __forceinline__ uint32_t smem_u32(const void* p) {
    uint32_t a;
    asm("{ .reg .u64 t; cvta.to.shared.u64 t, %1; cvt.u32.u64 %0, t; }" : "=r"(a) : "l"(p));
    return a;
}
__device__ __forceinline__ void cpa16(uint32_t dst, const void* src, uint32_t sz) {
    asm volatile("cp.async.cg.shared.global [%0], [%1], 16, %2;"
                 :: "r"(dst), "l"(src), "r"(sz) : "memory");
}
#define CP_COMMIT() asm volatile("cp.async.commit_group;" ::: "memory")
#define CP_WAIT1()  asm volatile("cp.async.wait_group 1;" ::: "memory")

#define LDSM4(r, a) \
    asm volatile("ldmatrix.sync.aligned.m8n8.x4.shared.b16 {%0,%1,%2,%3}, [%4];" \
        : "=r"((r)[0]), "=r"((r)[1]), "=r"((r)[2]), "=r"((r)[3]) : "r"(a))

__device__ __forceinline__ void mma16816(float* c, const uint32_t* a,
                                         uint32_t b0, uint32_t b1) {
    asm volatile(
        "mma.sync.aligned.m16n8k16.row.col.f32.f16.f16.f32 "
        "{%0,%1,%2,%3}, {%4,%5,%6,%7}, {%8,%9}, {%0,%1,%2,%3};"
        : "+f"(c[0]), "+f"(c[1]), "+f"(c[2]), "+f"(c[3])
        : "r"(a[0]), "r"(a[1]), "r"(a[2]), "r"(a[3]), "r"(b0), "r"(b1));
}

// HW tanh (MUFU.TANH, sm_75+): ~2^-11 accuracy, far below the fp16 noise floor.
__device__ __forceinline__ float tanh_fast(float x) {
    float r;
    asm("tanh.approx.f32 %0, %1;" : "=f"(r) : "f"(x));
    return r;
}
__device__ __forceinline__ float sigmoid_fast(float x) {
    return __fdividef(1.0f, 1.0f + __expf(-x));
}

// ---------------- combined prep kernel ----------------
#define PX_BLOCKS 2048    // 2048 blocks * 256 thr * 8 float4 = Mtot*Cdim/4

__global__ __launch_bounds__(256) void prep_all(
    const float* __restrict__ x,
    const float* __restrict__ wz, const float* __restrict__ wf, const float* __restrict__ wo)
{
    __shared__ float tile[32][33];
    if (blockIdx.x < PX_BLOCKS) {
        // x -> fp16, 8 float4 per thread, loads front-batched (MLP=8)
        const float4* xv = (const float4*)x;
        __half2* hp = (__half2*)g_xh;
        const size_t i0 = (size_t)blockIdx.x * 2048 + threadIdx.x;
        float4 v[8];
        #pragma unroll
        for (int j = 0; j < 8; j++) v[j] = xv[i0 + j * 256];
        #pragma unroll
        for (int j = 0; j < 8; j++) {
            const size_t i = i0 + j * 256;
            hp[i*2]   = __floats2half2_rn(v[j].x, v[j].y);
            hp[i*2+1] = __floats2half2_rn(v[j].z, v[j].w);
        }
    } else {
        const int bid = blockIdx.x - PX_BLOCKS;       // 0..1535
        const int gate = bid >> 9;
        const int rem = bid & 511;
        const int kk0 = (rem & 31) * 32, h0 = (rem >> 5) * 32;
        const float* W = (gate == 0) ? wz : ((gate == 1) ? wf : wo);
        const int tx = threadIdx.x & 31, ty = threadIdx.x >> 5;   // 32 x 8
        for (int i = ty; i < 32; i += 8)
            tile[i][tx] = W[(size_t)(kk0 + i) * Hdim + h0 + tx];
        __syncthreads();
        for (int i = ty; i < 32; i += 8) {
            float v = tile[tx][i];                                 // W[kk0+tx][h0+i]
            g_wt[gate][(size_t)(h0 + i) * 1024 + kk0 + tx] = __float2half(v);
        }
    }
}

// ---------------- HMMA GEMM (grid-tiled, BK=64 stages) ----------------
// grid (N/BN=4, M/BM=256, 3 gates), 256 threads (8 warps as 4m x 2n)
__global__ __launch_bounds__(256, 2) void gate_gemm_mma(
    const float* __restrict__ bz, const float* __restrict__ bf_,
    const float* __restrict__ bo)
{
    extern __shared__ char smem[];
    const uint32_t sb = smem_u32(smem);
    const int tid = threadIdx.x, lane = tid & 31, wid = tid >> 5;
    const int wm = wid & 3, wn = wid >> 2;
    const int gate = blockIdx.z;
    const int n0 = blockIdx.x * BN;
    const int m0 = blockIdx.y * BM;

    const float* bias = (gate == 0) ? bz : ((gate == 1) ? bf_ : bo);
    __half* outg      = (gate == 0) ? g_z : ((gate == 1) ? g_f : g_o);
    const __half* wt = g_wt[gate];

    const int lrow = tid >> 3;        // 0..31 (rows lrow, +32, +64, +96)
    const int lseg = tid & 7;         // 16B segment within 128B row

    auto load_stage = [&](int it) {
        const int kidx = it * 64;                 // 0..960 (never crosses 512)
        const int shift = (kidx < 512) ? 1 : 0;   // tap t-1 vs t
        const int acolB = ((kidx & 511) * 2) + lseg * 16;
        const int wcolB = kidx * 2 + lseg * 16;
        const uint32_t as = sb + (it % STAGES) * STG;
        const uint32_t bs = as + ASTG;
        #pragma unroll
        for (int h = 0; h < 4; h++) {
            const int r = lrow + h * 32;
            const int m = m0 + r;
            const char* src = (const char*)g_xh + (size_t)(m - shift) * 1024 + acolB;
            uint32_t sz = 16;
            if (shift && ((m & (Tlen - 1)) == 0)) { sz = 0; src = (const char*)g_xh; }
            cpa16(as + r * AROWB + lseg * 16, src, sz);
        }
        #pragma unroll
        for (int h = 0; h < 4; h++) {
            const int r = lrow + h * 32;
            const char* src = (const char*)wt + (size_t)(n0 + r) * 2048 + wcolB;
            cpa16(bs + r * AROWB + lseg * 16, src, 16);
        }
    };

    load_stage(0); CP_COMMIT();
    load_stage(1); CP_COMMIT();

    float acc[2][8][4];
    #pragma unroll
    for (int f = 0; f < 2; f++)
        #pragma unroll
        for (int n = 0; n < 8; n++)
            #pragma unroll
            for (int q = 0; q < 4; q++) acc[f][n][q] = 0.0f;

    const uint32_t aBase = (uint32_t)((wm * 32 + (lane & 15)) * AROWB + (lane >> 4) * 16);
    const uint32_t bBase = (uint32_t)((wn * 64 + (lane & 15)) * AROWB + (lane >> 4) * 16);

    for (int it = 0; it < NIT; it++) {
        CP_WAIT1();
        __syncthreads();
        // slot (it+2)%3 == (it-1)%3, fully consumed before the barrier above
        if (it + 2 < NIT) load_stage(it + 2);
        CP_COMMIT();

        const uint32_t as = sb + (it % STAGES) * STG;
        const uint32_t bs = as + ASTG;
        #pragma unroll
        for (int jk = 0; jk < 4; jk++) {
            uint32_t af[2][4], bg[4][4];
            LDSM4(af[0], as + aBase + jk * 32);
            LDSM4(af[1], as + aBase + 16 * AROWB + jk * 32);
            #pragma unroll
            for (int g = 0; g < 4; g++)
                LDSM4(bg[g], bs + bBase + g * 16 * AROWB + jk * 32);
            #pragma unroll
            for (int f = 0; f < 2; f++)
                #pragma unroll
                for (int nt = 0; nt < 8; nt++) {
                    const int g = nt >> 1, p = nt & 1;
                    mma16816(acc[f][nt], af[f], bg[g][p], bg[g][p + 2]);
                }
        }
    }

    // epilogue: bias + activation (HW tanh / fast sigmoid) + fp16 stores
    #pragma unroll
    for (int f = 0; f < 2; f++) {
        const int rbase = m0 + wm * 32 + f * 16 + (lane >> 2);
        #pragma unroll
        for (int nt = 0; nt < 8; nt++) {
            const int col = n0 + wn * 64 + nt * 8 + (lane & 3) * 2;
            const float b0 = __ldg(bias + col), b1 = __ldg(bias + col + 1);
            float v0 = acc[f][nt][0] + b0, v1 = acc[f][nt][1] + b1;
            float v2 = acc[f][nt][2] + b0, v3 = acc[f][nt][3] + b1;
            if (gate == 0) {
                v0 = tanh_fast(v0); v1 = tanh_fast(v1);
                v2 = tanh_fast(v2); v3 = tanh_fast(v3);
            } else {
                v0 = sigmoid_fast(v0); v1 = sigmoid_fast(v1);
                v2 = sigmoid_fast(v2); v3 = sigmoid_fast(v3);
            }
            *(__half2*)(outg + (size_t)rbase * Hdim + col)       = __floats2half2_rn(v0, v1);
            *(__half2*)(outg + (size_t)(rbase + 8) * Hdim + col) = __floats2half2_rn(v2, v3);
        }
    }
}

// ---------------- scan (chunked linear recurrence, half2-vectorized) ----------------
__global__ __launch_bounds__(256) void chunk_reduce()
{
    const int t2 = threadIdx.x;                   // half2 index: h = 2*t2, 2*t2+1
    const int c = blockIdx.x, b = blockIdx.y;
    size_t base = ((size_t)(b * Tlen + c * CHUNK) * Hdim >> 1) + t2;
    const __half2* F = (const __half2*)g_f;
    const __half2* Z = (const __half2*)g_z;
    float P0 = 1.f, P1 = 1.f, L0 = 0.f, L1 = 0.f;
    #pragma unroll 4
    for (int i = 0; i < CHUNK; i++) {
        const size_t idx = base + (size_t)i * (Hdim / 2);
        float2 f2 = __half22float2(F[idx]);
        float2 z2 = __half22float2(Z[idx]);
        L0 = fmaf(f2.x, L0, (1.0f - f2.x) * z2.x);
        L1 = fmaf(f2.y, L1, (1.0f - f2.y) * z2.y);
        P0 *= f2.x; P1 *= f2.y;
    }
    const size_t ci = (size_t)(b * NCH + c) * Hdim + 2 * t2;
    *(float2*)&g_P[ci] = make_float2(P0, P1);
    *(float2*)&g_L[ci] = make_float2(L0, L1);
}

// Prefix over chunk carries, double-buffered batch prefetch: load batch j+1
// while running batch j's serial FMAs -> one exposed memory latency total.
__global__ __launch_bounds__(256) void chunk_prefix()
{
    const int t2 = threadIdx.x;                   // 2 channels per thread
    const int b = blockIdx.x;
    const float2* P2 = (const float2*)g_P;
    const float2* L2 = (const float2*)g_L;
    float2* H2 = (float2*)g_hin;

    float2 P[2][8], L[2][8];
    auto fetch = [&](int buf, int c0) {
        #pragma unroll
        for (int j = 0; j < 8; j++) {
            const size_t idx = ((size_t)(b * NCH + c0 + j) * Hdim >> 1) + t2;
            P[buf][j] = P2[idx];
            L[buf][j] = L2[idx];
        }
    };

    fetch(0, 0);
    float2 hc = make_float2(0.f, 0.f);
    for (int c0 = 0; c0 < NCH; c0 += 8) {
        const int buf = (c0 >> 3) & 1;
        if (c0 + 8 < NCH) fetch(buf ^ 1, c0 + 8);
        #pragma unroll
        for (int j = 0; j < 8; j++) {
            const size_t idx = ((size_t)(b * NCH + c0 + j) * Hdim >> 1) + t2;
            H2[idx] = hc;
            hc.x = fmaf(P[buf][j].x, hc.x, L[buf][j].x);
            hc.y = fmaf(P[buf][j].y, hc.y, L[buf][j].y);
        }
    }
}

__global__ __launch_bounds__(256) void chunk_apply(float* __restrict__ out)
{
    const int t2 = threadIdx.x;
    const int c = blockIdx.x, b = blockIdx.y;
    float2 hc = *(const float2*)&g_hin[(size_t)(b * NCH + c) * Hdim + 2 * t2];
    size_t base = ((size_t)(b * Tlen + c * CHUNK) * Hdim >> 1) + t2;
    const __half2* F = (const __half2*)g_f;
    const __half2* Z = (const __half2*)g_z;
    const __half2* O = (const __half2*)g_o;
    #pragma unroll 4
    for (int i = 0; i < CHUNK; i++) {
        const size_t idx = base + (size_t)i * (Hdim / 2);
        float2 f2 = __half22float2(F[idx]);
        float2 z2 = __half22float2(Z[idx]);
        float2 o2 = __half22float2(O[idx]);
        hc.x = fmaf(f2.x, hc.x, (1.0f - f2.x) * z2.x);
        hc.y = fmaf(f2.y, hc.y, (1.0f - f2.y) * z2.y);
        ((float2*)out)[idx] = make_float2(hc.x * o2.x, hc.y * o2.y);
    }
}

// ---------------- launch ----------------
extern "C" void kernel_launch(void* const* d_in, const int* in_sizes, int n_in,
                              void* d_out, int out_size)
{
    const float* x  = (const float*)d_in[0];
    const float* wz = (const float*)d_in[1];
    const float* bz = (const float*)d_in[2];
    const float* wf = (const float*)d_in[3];
    const float* bf = (const float*)d_in[4];
    const float* wo = (const float*)d_in[5];
    const float* bo = (const float*)d_in[6];
    float* out = (float*)d_out;

    cudaFuncSetAttribute(gate_gemm_mma, cudaFuncAttributeMaxDynamicSharedMemorySize, SMEMT);

    prep_all<<<PX_BLOCKS + 1536, 256>>>(x, wz, wf, wo);

    gate_gemm_mma<<<dim3(Hdim / BN, Mtot / BM, 3), 256, SMEMT>>>(bz, bf, bo);

    chunk_reduce<<<dim3(NCH, Bsz), 256>>>();
    chunk_prefix<<<Bsz, 256>>>();
    chunk_apply<<<dim3(NCH, Bsz), 256>>>(out);
}